// round 4
// baseline (speedup 1.0000x reference)
#include <cuda_runtime.h>
#include <math.h>

// Problem constants
constexpr int N_NODES = 50000;
constexpr int F_IN    = 128;
constexpr int E_EDGES = 800000;
constexpr int DIM     = 64;
constexpr int G_GRAPH = 128;
constexpr int C_CLS   = 10;
constexpr float BN_EPS = 1e-5f;

// ----------------------------------------------------------------------------
// Scratch (static device globals — no runtime allocation).
// NOTE: these must ONLY be referenced from device code. Passing them as kernel
// arguments from host passes the host shadow address (silently readable on
// GB300 via ATS -> wrong results, no trap).
// ----------------------------------------------------------------------------
__device__ float g_agg[N_NODES * F_IN];    // conv input+aggregate
__device__ float g_u[N_NODES * DIM];       // MLP hidden
__device__ float g_h[N_NODES * DIM];       // pre-BN layer output (post outer ReLU)
__device__ float g_sum[DIM];
__device__ float g_sumsq[DIM];
__device__ float g_scale[DIM];             // BN fused scale
__device__ float g_shift[DIM];             // BN fused shift
__device__ float g_pooled[G_GRAPH * DIM];

enum { BUF_AGG = 0, BUF_U = 1, BUF_H = 2 };
__device__ __forceinline__ float* get_buf(int id) {
    return id == BUF_AGG ? g_agg : (id == BUF_U ? g_u : g_h);
}

// ----------------------------------------------------------------------------
// Small utility kernels
// ----------------------------------------------------------------------------
__global__ void zero_stats_kernel() {
    int j = threadIdx.x;
    if (j < DIM) { g_sum[j] = 0.f; g_sumsq[j] = 0.f; }
}

__global__ void zero_pooled_kernel() {
    int t = blockIdx.x * blockDim.x + threadIdx.x;
    if (t < G_GRAPH * DIM) g_pooled[t] = 0.f;
}

__global__ void bn_params_kernel(const float* __restrict__ gamma,
                                 const float* __restrict__ beta) {
    int j = threadIdx.x;
    if (j >= DIM) return;
    const float inv_n = 1.0f / (float)N_NODES;
    float mean = g_sum[j] * inv_n;
    float var  = g_sumsq[j] * inv_n - mean * mean;
    float rstd = rsqrtf(var + BN_EPS);
    float sc = gamma[j] * rstd;
    g_scale[j] = sc;
    g_shift[j] = beta[j] - mean * sc;
}

// copy x -> agg (layer-1 self term, 128 features)
__global__ void copy_x_kernel(const float* __restrict__ x) {
    int t = blockIdx.x * blockDim.x + threadIdx.x;
    if (t < N_NODES * F_IN / 4) {
        ((float4*)g_agg)[t] = ((const float4*)x)[t];
    }
}

// agg = bn(h)  (self term, layers 2..5, 64 features)
__global__ void init_agg_bn_kernel() {
    int t = blockIdx.x * blockDim.x + threadIdx.x;
    if (t >= N_NODES * (DIM / 4)) return;
    int c = t & 15;
    float4 v  = ((const float4*)g_h)[t];
    float4 sc = ((const float4*)g_scale)[c];
    float4 sh = ((const float4*)g_shift)[c];
    v.x = fmaf(v.x, sc.x, sh.x);
    v.y = fmaf(v.y, sc.y, sh.y);
    v.z = fmaf(v.z, sc.z, sh.z);
    v.w = fmaf(v.w, sc.w, sh.w);
    ((float4*)g_agg)[t] = v;
}

// ----------------------------------------------------------------------------
// Edge scatter (segment_sum of source feats at targets)
// ----------------------------------------------------------------------------
// Layer 1: reads x directly (no BN). One thread per (edge, float4 chunk of 128).
__global__ void scatter128_kernel(const int* __restrict__ ei,
                                  const float* __restrict__ x) {
    int t = blockIdx.x * blockDim.x + threadIdx.x;
    if (t >= E_EDGES * 32) return;
    int e = t >> 5;
    int c = t & 31;
    int src = ei[e];
    int dst = ei[E_EDGES + e];
    float4 v = ((const float4*)x)[src * 32 + c];
    float* p = g_agg + dst * F_IN + c * 4;
    atomicAdd(p + 0, v.x);
    atomicAdd(p + 1, v.y);
    atomicAdd(p + 2, v.z);
    atomicAdd(p + 3, v.w);
}

// Layers 2..5: reads bn(h[src]). One thread per (edge, float4 chunk of 64).
__global__ void scatter64_kernel(const int* __restrict__ ei) {
    int t = blockIdx.x * blockDim.x + threadIdx.x;
    if (t >= E_EDGES * 16) return;
    int e = t >> 4;
    int c = t & 15;
    int src = ei[e];
    int dst = ei[E_EDGES + e];
    float4 v  = ((const float4*)g_h)[src * 16 + c];
    float4 sc = ((const float4*)g_scale)[c];
    float4 sh = ((const float4*)g_shift)[c];
    v.x = fmaf(v.x, sc.x, sh.x);
    v.y = fmaf(v.y, sc.y, sh.y);
    v.z = fmaf(v.z, sc.z, sh.z);
    v.w = fmaf(v.w, sc.w, sh.w);
    float* p = g_agg + dst * DIM + c * 4;
    atomicAdd(p + 0, v.x);
    atomicAdd(p + 1, v.y);
    atomicAdd(p + 2, v.z);
    atomicAdd(p + 3, v.w);
}

// ----------------------------------------------------------------------------
// GEMM + bias + ReLU: out[N,DIM] = relu(in[N,K] @ W[K,DIM] + b)
// One thread per row, 64 fp32 accumulators, weights in shared (broadcast).
// Buffers selected by template id and resolved IN DEVICE CODE.
// ----------------------------------------------------------------------------
template <int K, int SRC, int DST>
__global__ void gemm_relu_kernel(const float* __restrict__ W,
                                 const float* __restrict__ bias) {
    const float* in = get_buf(SRC);
    float*       out = get_buf(DST);

    __shared__ float ws[K * DIM];
    __shared__ float bs[DIM];
    int tid = threadIdx.x;
    for (int i = tid; i < K * DIM; i += blockDim.x) ws[i] = W[i];
    if (tid < DIM) bs[tid] = bias[tid];
    __syncthreads();

    int row = blockIdx.x * blockDim.x + tid;
    if (row >= N_NODES) return;

    float acc[DIM];
#pragma unroll
    for (int j = 0; j < DIM; j++) acc[j] = bs[j];

    const float4* inr = (const float4*)(in + row * K);
#pragma unroll 2
    for (int k4 = 0; k4 < K / 4; k4++) {
        float4 a = inr[k4];
        const float* w0 = &ws[(4 * k4 + 0) * DIM];
        const float* w1 = &ws[(4 * k4 + 1) * DIM];
        const float* w2 = &ws[(4 * k4 + 2) * DIM];
        const float* w3 = &ws[(4 * k4 + 3) * DIM];
#pragma unroll
        for (int j = 0; j < DIM; j++) {
            float s = acc[j];
            s = fmaf(a.x, w0[j], s);
            s = fmaf(a.y, w1[j], s);
            s = fmaf(a.z, w2[j], s);
            s = fmaf(a.w, w3[j], s);
            acc[j] = s;
        }
    }

    float4* o = (float4*)(out + row * DIM);
#pragma unroll
    for (int j4 = 0; j4 < DIM / 4; j4++) {
        float4 v;
        v.x = fmaxf(acc[4 * j4 + 0], 0.f);
        v.y = fmaxf(acc[4 * j4 + 1], 0.f);
        v.z = fmaxf(acc[4 * j4 + 2], 0.f);
        v.w = fmaxf(acc[4 * j4 + 3], 0.f);
        o[j4] = v;
    }
}

// ----------------------------------------------------------------------------
// Column sums / sumsq of g_h (coalesced; feature = tid % 64 is loop-invariant)
// ----------------------------------------------------------------------------
__global__ void stats_kernel() {
    int t0 = blockIdx.x * blockDim.x + threadIdx.x;
    int stride = gridDim.x * blockDim.x;   // multiple of 64
    float s = 0.f, s2 = 0.f;
    for (int i = t0; i < N_NODES * DIM; i += stride) {
        float v = g_h[i];
        s += v;
        s2 += v * v;
    }
    __shared__ float sh[256], sh2[256];
    sh[threadIdx.x] = s;
    sh2[threadIdx.x] = s2;
    __syncthreads();
    if (threadIdx.x < 64) {
        float a  = sh[threadIdx.x]  + sh[threadIdx.x + 64]  + sh[threadIdx.x + 128]  + sh[threadIdx.x + 192];
        float a2 = sh2[threadIdx.x] + sh2[threadIdx.x + 64] + sh2[threadIdx.x + 128] + sh2[threadIdx.x + 192];
        atomicAdd(&g_sum[threadIdx.x], a);
        atomicAdd(&g_sumsq[threadIdx.x], a2);
    }
}

// ----------------------------------------------------------------------------
// Global add pool of bn(h) by graph id
// ----------------------------------------------------------------------------
__global__ void pool_kernel(const int* __restrict__ batch) {
    int t = blockIdx.x * blockDim.x + threadIdx.x;
    if (t >= N_NODES * (DIM / 4)) return;
    int n = t >> 4;
    int c = t & 15;
    float4 v  = ((const float4*)g_h)[t];
    float4 sc = ((const float4*)g_scale)[c];
    float4 sh = ((const float4*)g_shift)[c];
    v.x = fmaf(v.x, sc.x, sh.x);
    v.y = fmaf(v.y, sc.y, sh.y);
    v.z = fmaf(v.z, sc.z, sh.z);
    v.w = fmaf(v.w, sc.w, sh.w);
    int g = batch[n];
    float* p = g_pooled + g * DIM + c * 4;
    atomicAdd(p + 0, v.x);
    atomicAdd(p + 1, v.y);
    atomicAdd(p + 2, v.z);
    atomicAdd(p + 3, v.w);
}

// ----------------------------------------------------------------------------
// Head: z = relu(pooled@fc1+b); logits = z@fc2+b; log_softmax
// ----------------------------------------------------------------------------
__global__ void head_kernel(const float* __restrict__ fc1w, const float* __restrict__ fc1b,
                            const float* __restrict__ fc2w, const float* __restrict__ fc2b,
                            float* __restrict__ out) {
    int g = threadIdx.x;
    if (g >= G_GRAPH) return;
    float p[DIM];
#pragma unroll
    for (int k = 0; k < DIM; k++) p[k] = g_pooled[g * DIM + k];

    float z[DIM];
#pragma unroll
    for (int j = 0; j < DIM; j++) z[j] = fc1b[j];
    for (int k = 0; k < DIM; k++) {
        float a = p[k];
#pragma unroll
        for (int j = 0; j < DIM; j++) z[j] = fmaf(a, fc1w[k * DIM + j], z[j]);
    }
#pragma unroll
    for (int j = 0; j < DIM; j++) z[j] = fmaxf(z[j], 0.f);

    float logit[C_CLS];
#pragma unroll
    for (int c = 0; c < C_CLS; c++) logit[c] = fc2b[c];
    for (int j = 0; j < DIM; j++) {
        float a = z[j];
#pragma unroll
        for (int c = 0; c < C_CLS; c++) logit[c] = fmaf(a, fc2w[j * C_CLS + c], logit[c]);
    }

    float m = logit[0];
#pragma unroll
    for (int c = 1; c < C_CLS; c++) m = fmaxf(m, logit[c]);
    float se = 0.f;
#pragma unroll
    for (int c = 0; c < C_CLS; c++) se += expf(logit[c] - m);
    float lse = m + logf(se);
#pragma unroll
    for (int c = 0; c < C_CLS; c++) out[g * C_CLS + c] = logit[c] - lse;
}

// ----------------------------------------------------------------------------
// Launch
// ----------------------------------------------------------------------------
extern "C" void kernel_launch(void* const* d_in, const int* in_sizes, int n_in,
                              void* d_out, int out_size) {
    const float* x     = (const float*)d_in[0];
    const int*   ei    = (const int*)d_in[1];
    const int*   batch = (const int*)d_in[2];
    const float* W1a = (const float*)d_in[3];
    const float* b1a = (const float*)d_in[4];
    const float* W1b = (const float*)d_in[5];
    const float* b1b = (const float*)d_in[6];
    const float* Wa  = (const float*)d_in[7];   // [4,64,64]
    const float* ba  = (const float*)d_in[8];   // [4,64]
    const float* Wb  = (const float*)d_in[9];
    const float* bb  = (const float*)d_in[10];
    const float* gammas = (const float*)d_in[11]; // [5,64]
    const float* betas  = (const float*)d_in[12];
    const float* fc1w = (const float*)d_in[13];
    const float* fc1b = (const float*)d_in[14];
    const float* fc2w = (const float*)d_in[15];
    const float* fc2b = (const float*)d_in[16];
    float* out = (float*)d_out;

    const int TB = 256;
    const int gemm_blocks = (N_NODES + 127) / 128;

    // ---------------- Layer 1 (K = 128) ----------------
    copy_x_kernel<<<(N_NODES * F_IN / 4 + TB - 1) / TB, TB>>>(x);
    scatter128_kernel<<<(E_EDGES * 32 + TB - 1) / TB, TB>>>(ei, x);
    zero_stats_kernel<<<1, 64>>>();
    gemm_relu_kernel<128, BUF_AGG, BUF_U><<<gemm_blocks, 128>>>(W1a, b1a);
    gemm_relu_kernel<64, BUF_U, BUF_H><<<gemm_blocks, 128>>>(W1b, b1b);
    stats_kernel<<<296, 256>>>();
    bn_params_kernel<<<1, 64>>>(gammas + 0 * DIM, betas + 0 * DIM);

    // ---------------- Layers 2..5 (K = 64) ----------------
    for (int L = 0; L < 4; L++) {
        init_agg_bn_kernel<<<(N_NODES * 16 + TB - 1) / TB, TB>>>();
        scatter64_kernel<<<(E_EDGES * 16 + TB - 1) / TB, TB>>>(ei);
        zero_stats_kernel<<<1, 64>>>();
        gemm_relu_kernel<64, BUF_AGG, BUF_U><<<gemm_blocks, 128>>>(Wa + L * DIM * DIM, ba + L * DIM);
        gemm_relu_kernel<64, BUF_U, BUF_H><<<gemm_blocks, 128>>>(Wb + L * DIM * DIM, bb + L * DIM);
        stats_kernel<<<296, 256>>>();
        bn_params_kernel<<<1, 64>>>(gammas + (L + 1) * DIM, betas + (L + 1) * DIM);
    }

    // ---------------- Pool + head ----------------
    zero_pooled_kernel<<<(G_GRAPH * DIM + TB - 1) / TB, TB>>>();
    pool_kernel<<<(N_NODES * 16 + TB - 1) / TB, TB>>>(batch);
    head_kernel<<<1, 128>>>(fc1w, fc1b, fc2w, fc2b, out);
}

// round 5
// speedup vs baseline: 1.4596x; 1.4596x over previous
#include <cuda_runtime.h>
#include <math.h>

// Problem constants
constexpr int N_NODES = 50000;
constexpr int F_IN    = 128;
constexpr int E_EDGES = 800000;
constexpr int DIM     = 64;
constexpr int G_GRAPH = 128;
constexpr int C_CLS   = 10;
constexpr float BN_EPS = 1e-5f;

// ----------------------------------------------------------------------------
// Device-global scratch (resolved ONLY in device code; host passes IDs).
// ----------------------------------------------------------------------------
__device__ float g_agg[N_NODES * DIM];     // aggregate buffer (self + edge sums)
__device__ float g_u[N_NODES * DIM];       // xw (layer1) / MLP hidden
__device__ float g_h[N_NODES * DIM];       // layer output (post outer ReLU, pre-BN)
__device__ float g_sum[DIM];
__device__ float g_sumsq[DIM];
__device__ float g_scale[DIM];             // BN fused scale for current layer
__device__ float g_shift[DIM];             // BN fused shift
__device__ float g_Wp[DIM * DIM];          // folded weights diag(scale) @ Wa_next
__device__ float g_cvec[DIM];              // shift @ Wa_next
__device__ int   g_deg[N_NODES];           // in-degree (dst counts)
__device__ int   g_gcnt[G_GRAPH];          // nodes per graph
__device__ float g_pooled[G_GRAPH * DIM];  // raw pooled h (BN applied in head)

enum { BUF_AGG = 0, BUF_U = 1, BUF_H = 2 };
__device__ __forceinline__ float* get_buf(int id) {
    return id == BUF_AGG ? g_agg : (id == BUF_U ? g_u : g_h);
}

__device__ __forceinline__ void red_v4(float* p, float4 v) {
    asm volatile("red.global.add.v4.f32 [%0], {%1,%2,%3,%4};"
                 :: "l"(p), "f"(v.x), "f"(v.y), "f"(v.z), "f"(v.w) : "memory");
}

// ----------------------------------------------------------------------------
// Once-per-launch: degrees + graph counts
// ----------------------------------------------------------------------------
__global__ void zero_counts_kernel() {
    int t = blockIdx.x * blockDim.x + threadIdx.x;
    if (t < N_NODES) g_deg[t] = 0;
    if (t < G_GRAPH) g_gcnt[t] = 0;
}
__global__ void deg_kernel(const int* __restrict__ ei) {
    int t = blockIdx.x * blockDim.x + threadIdx.x;
    if (t < E_EDGES) atomicAdd(&g_deg[ei[E_EDGES + t]], 1);
}
__global__ void gcnt_kernel(const int* __restrict__ batch) {
    int t = blockIdx.x * blockDim.x + threadIdx.x;
    if (t < N_NODES) atomicAdd(&g_gcnt[batch[t]], 1);
}

// ----------------------------------------------------------------------------
// Tiny per-layer kernels
// ----------------------------------------------------------------------------
__global__ void zero_stats_kernel() {
    int j = threadIdx.x;
    if (j < DIM) { g_sum[j] = 0.f; g_sumsq[j] = 0.f; }
}
__global__ void zero_pooled_kernel() {
    int t = blockIdx.x * blockDim.x + threadIdx.x;
    if (t < G_GRAPH * DIM) g_pooled[t] = 0.f;
}
__global__ void bn_params_kernel(const float* __restrict__ gamma,
                                 const float* __restrict__ beta) {
    int j = threadIdx.x;
    if (j >= DIM) return;
    const float inv_n = 1.0f / (float)N_NODES;
    float mean = g_sum[j] * inv_n;
    float var  = g_sumsq[j] * inv_n - mean * mean;
    float rstd = rsqrtf(var + BN_EPS);
    float sc = gamma[j] * rstd;
    g_scale[j] = sc;
    g_shift[j] = beta[j] - mean * sc;
}
// Fold BN into next conv's first weight: Wp = diag(scale)@Wa, cvec = shift@Wa
__global__ void fold_kernel(const float* __restrict__ Wa) {
    int tid = threadIdx.x;   // single block of 256
    for (int i = tid; i < DIM * DIM; i += 256)
        g_Wp[i] = g_scale[i >> 6] * Wa[i];
    if (tid < DIM) {
        float c = 0.f;
        for (int k = 0; k < DIM; k++) c = fmaf(g_shift[k], Wa[k * DIM + tid], c);
        g_cvec[tid] = c;
    }
}

// ----------------------------------------------------------------------------
// Edge scatter with vector atomics: g_agg[dst] += src_buf[src]  (64 feats)
// ----------------------------------------------------------------------------
template <int SRC>
__global__ void scatter_kernel(const int* __restrict__ ei) {
    int t = blockIdx.x * blockDim.x + threadIdx.x;
    if (t >= E_EDGES * 16) return;
    int e = t >> 4;
    int c = t & 15;
    int src = __ldg(ei + e);
    int dst = __ldg(ei + E_EDGES + e);
    const float* sp = get_buf(SRC);
    float4 v = ((const float4*)sp)[src * 16 + c];
    red_v4(g_agg + dst * DIM + c * 4, v);
}

// ----------------------------------------------------------------------------
// GEMM family: 256 threads = 128 rows x 2 column-halves; 32 accumulators each.
// Weights staged in shared (broadcast LDS).
// ----------------------------------------------------------------------------

// xw = x @ W1a  (K=128, no bias/relu), dup-write to g_u and g_agg
__global__ __launch_bounds__(256) void gemm_xw_kernel(const float* __restrict__ x,
                                                      const float* __restrict__ W) {
    __shared__ float ws[F_IN * DIM];
    int tid = threadIdx.x;
    for (int i = tid; i < F_IN * DIM; i += 256) ws[i] = W[i];
    __syncthreads();

    int row  = blockIdx.x * 128 + (tid >> 1);
    int half = (tid & 1) * 32;
    if (row >= N_NODES) return;

    float acc[32];
#pragma unroll
    for (int j = 0; j < 32; j++) acc[j] = 0.f;

    const float4* inr = (const float4*)(x + row * F_IN);
#pragma unroll 4
    for (int k4 = 0; k4 < F_IN / 4; k4++) {
        float4 a = inr[k4];
        const float* w0 = &ws[(4 * k4 + 0) * DIM + half];
        const float* w1 = &ws[(4 * k4 + 1) * DIM + half];
        const float* w2 = &ws[(4 * k4 + 2) * DIM + half];
        const float* w3 = &ws[(4 * k4 + 3) * DIM + half];
#pragma unroll
        for (int j = 0; j < 32; j++) {
            float s = acc[j];
            s = fmaf(a.x, w0[j], s);
            s = fmaf(a.y, w1[j], s);
            s = fmaf(a.z, w2[j], s);
            s = fmaf(a.w, w3[j], s);
            acc[j] = s;
        }
    }
    float4* ou = (float4*)(g_u + row * DIM + half);
    float4* oa = (float4*)(g_agg + row * DIM + half);
#pragma unroll
    for (int j4 = 0; j4 < 8; j4++) {
        float4 v = make_float4(acc[4*j4], acc[4*j4+1], acc[4*j4+2], acc[4*j4+3]);
        ou[j4] = v;
        oa[j4] = v;
    }
}

// Layer-1 MLP stage 2: h = relu( relu(agg + b1a) @ W1b + b1b ); dup to g_h,g_agg.
// In-place on g_agg: pair threads share a warp -> __syncwarp before store.
__global__ __launch_bounds__(256) void gemm_l1b_kernel(const float* __restrict__ W,
                                                       const float* __restrict__ bin,
                                                       const float* __restrict__ bout) {
    __shared__ float ws[DIM * DIM];
    __shared__ float bi[DIM], bo[DIM];
    int tid = threadIdx.x;
    for (int i = tid; i < DIM * DIM; i += 256) ws[i] = W[i];
    if (tid < DIM) { bi[tid] = bin[tid]; bo[tid] = bout[tid]; }
    __syncthreads();

    int row  = blockIdx.x * 128 + (tid >> 1);
    int half = (tid & 1) * 32;
    if (row >= N_NODES) return;

    float acc[32];
#pragma unroll
    for (int j = 0; j < 32; j++) acc[j] = 0.f;

    const float4* inr = (const float4*)(g_agg + row * DIM);
#pragma unroll
    for (int k4 = 0; k4 < DIM / 4; k4++) {
        float4 a = inr[k4];
        a.x = fmaxf(a.x + bi[4*k4+0], 0.f);
        a.y = fmaxf(a.y + bi[4*k4+1], 0.f);
        a.z = fmaxf(a.z + bi[4*k4+2], 0.f);
        a.w = fmaxf(a.w + bi[4*k4+3], 0.f);
        const float* w0 = &ws[(4 * k4 + 0) * DIM + half];
        const float* w1 = &ws[(4 * k4 + 1) * DIM + half];
        const float* w2 = &ws[(4 * k4 + 2) * DIM + half];
        const float* w3 = &ws[(4 * k4 + 3) * DIM + half];
#pragma unroll
        for (int j = 0; j < 32; j++) {
            float s = acc[j];
            s = fmaf(a.x, w0[j], s);
            s = fmaf(a.y, w1[j], s);
            s = fmaf(a.z, w2[j], s);
            s = fmaf(a.w, w3[j], s);
            acc[j] = s;
        }
    }
    __syncwarp(__activemask());   // pair threads done reading g_agg row
    float4* oh = (float4*)(g_h + row * DIM + half);
    float4* oa = (float4*)(g_agg + row * DIM + half);
#pragma unroll
    for (int j4 = 0; j4 < 8; j4++) {
        float4 v;
        v.x = fmaxf(acc[4*j4+0] + bo[half + 4*j4+0], 0.f);
        v.y = fmaxf(acc[4*j4+1] + bo[half + 4*j4+1], 0.f);
        v.z = fmaxf(acc[4*j4+2] + bo[half + 4*j4+2], 0.f);
        v.w = fmaxf(acc[4*j4+3] + bo[half + 4*j4+3], 0.f);
        oh[j4] = v;
        oa[j4] = v;
    }
}

// Layers 2-5 MLP stage 1 (BN folded): u = relu( agg @ Wp + (1+deg)*cvec + ba )
__global__ __launch_bounds__(256) void gemm_c_kernel(const float* __restrict__ ba) {
    __shared__ float ws[DIM * DIM];
    __shared__ float cv[DIM], bs[DIM];
    int tid = threadIdx.x;
    for (int i = tid; i < DIM * DIM; i += 256) ws[i] = g_Wp[i];
    if (tid < DIM) { cv[tid] = g_cvec[tid]; bs[tid] = ba[tid]; }
    __syncthreads();

    int row  = blockIdx.x * 128 + (tid >> 1);
    int half = (tid & 1) * 32;
    if (row >= N_NODES) return;

    float acc[32];
#pragma unroll
    for (int j = 0; j < 32; j++) acc[j] = 0.f;

    const float4* inr = (const float4*)(g_agg + row * DIM);
#pragma unroll
    for (int k4 = 0; k4 < DIM / 4; k4++) {
        float4 a = inr[k4];
        const float* w0 = &ws[(4 * k4 + 0) * DIM + half];
        const float* w1 = &ws[(4 * k4 + 1) * DIM + half];
        const float* w2 = &ws[(4 * k4 + 2) * DIM + half];
        const float* w3 = &ws[(4 * k4 + 3) * DIM + half];
#pragma unroll
        for (int j = 0; j < 32; j++) {
            float s = acc[j];
            s = fmaf(a.x, w0[j], s);
            s = fmaf(a.y, w1[j], s);
            s = fmaf(a.z, w2[j], s);
            s = fmaf(a.w, w3[j], s);
            acc[j] = s;
        }
    }
    float dp1 = 1.0f + (float)g_deg[row];
    float4* ou = (float4*)(g_u + row * DIM + half);
#pragma unroll
    for (int j4 = 0; j4 < 8; j4++) {
        float4 v;
        v.x = fmaxf(fmaf(dp1, cv[half+4*j4+0], acc[4*j4+0]) + bs[half+4*j4+0], 0.f);
        v.y = fmaxf(fmaf(dp1, cv[half+4*j4+1], acc[4*j4+1]) + bs[half+4*j4+1], 0.f);
        v.z = fmaxf(fmaf(dp1, cv[half+4*j4+2], acc[4*j4+2]) + bs[half+4*j4+2], 0.f);
        v.w = fmaxf(fmaf(dp1, cv[half+4*j4+3], acc[4*j4+3]) + bs[half+4*j4+3], 0.f);
        ou[j4] = v;
    }
}

// MLP stage 2 (layers 2-5): h = relu(u @ Wb + bb); dup-write g_h and g_agg.
__global__ __launch_bounds__(256) void gemm_d_kernel(const float* __restrict__ W,
                                                     const float* __restrict__ bout) {
    __shared__ float ws[DIM * DIM];
    __shared__ float bo[DIM];
    int tid = threadIdx.x;
    for (int i = tid; i < DIM * DIM; i += 256) ws[i] = W[i];
    if (tid < DIM) bo[tid] = bout[tid];
    __syncthreads();

    int row  = blockIdx.x * 128 + (tid >> 1);
    int half = (tid & 1) * 32;
    if (row >= N_NODES) return;

    float acc[32];
#pragma unroll
    for (int j = 0; j < 32; j++) acc[j] = 0.f;

    const float4* inr = (const float4*)(g_u + row * DIM);
#pragma unroll
    for (int k4 = 0; k4 < DIM / 4; k4++) {
        float4 a = inr[k4];
        const float* w0 = &ws[(4 * k4 + 0) * DIM + half];
        const float* w1 = &ws[(4 * k4 + 1) * DIM + half];
        const float* w2 = &ws[(4 * k4 + 2) * DIM + half];
        const float* w3 = &ws[(4 * k4 + 3) * DIM + half];
#pragma unroll
        for (int j = 0; j < 32; j++) {
            float s = acc[j];
            s = fmaf(a.x, w0[j], s);
            s = fmaf(a.y, w1[j], s);
            s = fmaf(a.z, w2[j], s);
            s = fmaf(a.w, w3[j], s);
            acc[j] = s;
        }
    }
    float4* oh = (float4*)(g_h + row * DIM + half);
    float4* oa = (float4*)(g_agg + row * DIM + half);
#pragma unroll
    for (int j4 = 0; j4 < 8; j4++) {
        float4 v;
        v.x = fmaxf(acc[4*j4+0] + bo[half + 4*j4+0], 0.f);
        v.y = fmaxf(acc[4*j4+1] + bo[half + 4*j4+1], 0.f);
        v.z = fmaxf(acc[4*j4+2] + bo[half + 4*j4+2], 0.f);
        v.w = fmaxf(acc[4*j4+3] + bo[half + 4*j4+3], 0.f);
        oh[j4] = v;
        oa[j4] = v;
    }
}

// ----------------------------------------------------------------------------
// Column sums / sumsq of g_h (float4, shared tree reduce, vector final red)
// ----------------------------------------------------------------------------
__global__ void stats_kernel() {
    int tid = threadIdx.x;
    int t0 = blockIdx.x * 256 + tid;
    int stride = gridDim.x * 256;        // multiple of 16
    float4 s  = make_float4(0,0,0,0);
    float4 s2 = make_float4(0,0,0,0);
    const float4* hp = (const float4*)g_h;
    for (int i = t0; i < N_NODES * 16; i += stride) {
        float4 v = hp[i];
        s.x += v.x; s.y += v.y; s.z += v.z; s.w += v.w;
        s2.x = fmaf(v.x, v.x, s2.x); s2.y = fmaf(v.y, v.y, s2.y);
        s2.z = fmaf(v.z, v.z, s2.z); s2.w = fmaf(v.w, v.w, s2.w);
    }
    __shared__ float4 sh[256], sh2[256];
    sh[tid] = s; sh2[tid] = s2;
    __syncthreads();
    for (int off = 128; off >= 16; off >>= 1) {
        if (tid < off) {
            float4 a = sh[tid], b = sh[tid + off];
            sh[tid] = make_float4(a.x+b.x, a.y+b.y, a.z+b.z, a.w+b.w);
            float4 c = sh2[tid], d = sh2[tid + off];
            sh2[tid] = make_float4(c.x+d.x, c.y+d.y, c.z+d.z, c.w+d.w);
        }
        __syncthreads();
    }
    if (tid < 16) {
        red_v4(g_sum   + tid * 4, sh[tid]);
        red_v4(g_sumsq + tid * 4, sh2[tid]);
    }
}

// ----------------------------------------------------------------------------
// Global add pool (raw h; BN applied in head via scale/shift + counts)
// ----------------------------------------------------------------------------
__global__ void pool_kernel(const int* __restrict__ batch) {
    int t = blockIdx.x * blockDim.x + threadIdx.x;
    if (t >= N_NODES * 16) return;
    int n = t >> 4;
    int c = t & 15;
    float4 v = ((const float4*)g_h)[t];
    red_v4(g_pooled + batch[n] * DIM + c * 4, v);
}

// ----------------------------------------------------------------------------
// Head: apply BN to pooled sums, fc1+relu, fc2, log_softmax
// ----------------------------------------------------------------------------
__global__ void head_kernel(const float* __restrict__ fc1w, const float* __restrict__ fc1b,
                            const float* __restrict__ fc2w, const float* __restrict__ fc2b,
                            float* __restrict__ out) {
    int g = threadIdx.x;
    if (g >= G_GRAPH) return;
    float cnt = (float)g_gcnt[g];
    float p[DIM];
#pragma unroll
    for (int k = 0; k < DIM; k++)
        p[k] = fmaf(g_pooled[g * DIM + k], g_scale[k], cnt * g_shift[k]);

    float z[DIM];
#pragma unroll
    for (int j = 0; j < DIM; j++) z[j] = fc1b[j];
    for (int k = 0; k < DIM; k++) {
        float a = p[k];
#pragma unroll
        for (int j = 0; j < DIM; j++) z[j] = fmaf(a, fc1w[k * DIM + j], z[j]);
    }
#pragma unroll
    for (int j = 0; j < DIM; j++) z[j] = fmaxf(z[j], 0.f);

    float logit[C_CLS];
#pragma unroll
    for (int c = 0; c < C_CLS; c++) logit[c] = fc2b[c];
    for (int j = 0; j < DIM; j++) {
        float a = z[j];
#pragma unroll
        for (int c = 0; c < C_CLS; c++) logit[c] = fmaf(a, fc2w[j * C_CLS + c], logit[c]);
    }

    float m = logit[0];
#pragma unroll
    for (int c = 1; c < C_CLS; c++) m = fmaxf(m, logit[c]);
    float se = 0.f;
#pragma unroll
    for (int c = 0; c < C_CLS; c++) se += expf(logit[c] - m);
    float lse = m + logf(se);
#pragma unroll
    for (int c = 0; c < C_CLS; c++) out[g * C_CLS + c] = logit[c] - lse;
}

// ----------------------------------------------------------------------------
// Launch
// ----------------------------------------------------------------------------
extern "C" void kernel_launch(void* const* d_in, const int* in_sizes, int n_in,
                              void* d_out, int out_size) {
    const float* x     = (const float*)d_in[0];
    const int*   ei    = (const int*)d_in[1];
    const int*   batch = (const int*)d_in[2];
    const float* W1a = (const float*)d_in[3];
    const float* b1a = (const float*)d_in[4];
    const float* W1b = (const float*)d_in[5];
    const float* b1b = (const float*)d_in[6];
    const float* Wa  = (const float*)d_in[7];   // [4,64,64]
    const float* ba  = (const float*)d_in[8];   // [4,64]
    const float* Wb  = (const float*)d_in[9];
    const float* bb  = (const float*)d_in[10];
    const float* gammas = (const float*)d_in[11]; // [5,64]
    const float* betas  = (const float*)d_in[12];
    const float* fc1w = (const float*)d_in[13];
    const float* fc1b = (const float*)d_in[14];
    const float* fc2w = (const float*)d_in[15];
    const float* fc2b = (const float*)d_in[16];
    float* out = (float*)d_out;

    const int TB = 256;
    const int gemm_blocks = (N_NODES + 127) / 128;       // 391
    const int scat_blocks = (E_EDGES * 16) / TB;         // 50000

    // Once-per-launch structural counts
    zero_counts_kernel<<<(N_NODES + TB - 1) / TB, TB>>>();
    deg_kernel<<<(E_EDGES + TB - 1) / TB, TB>>>(ei);
    gcnt_kernel<<<(N_NODES + TB - 1) / TB, TB>>>(batch);

    // ---------------- Layer 1 ----------------
    gemm_xw_kernel<<<gemm_blocks, 256>>>(x, W1a);        // g_u = g_agg = x@W1a
    scatter_kernel<BUF_U><<<scat_blocks, TB>>>(ei);       // g_agg += xw[src]
    gemm_l1b_kernel<<<gemm_blocks, 256>>>(W1b, b1a, b1b); // g_h, g_agg = mlp out
    zero_stats_kernel<<<1, 64>>>();
    stats_kernel<<<296, 256>>>();
    bn_params_kernel<<<1, 64>>>(gammas, betas);
    fold_kernel<<<1, 256>>>(Wa);                          // fold BN1 into Wa[0]

    // ---------------- Layers 2..5 ----------------
    for (int L = 0; L < 4; L++) {
        scatter_kernel<BUF_H><<<scat_blocks, TB>>>(ei);   // g_agg += h[src]
        gemm_c_kernel<<<gemm_blocks, 256>>>(ba + L * DIM);
        gemm_d_kernel<<<gemm_blocks, 256>>>(Wb + L * DIM * DIM, bb + L * DIM);
        zero_stats_kernel<<<1, 64>>>();
        stats_kernel<<<296, 256>>>();
        bn_params_kernel<<<1, 64>>>(gammas + (L + 1) * DIM, betas + (L + 1) * DIM);
        if (L < 3) fold_kernel<<<1, 256>>>(Wa + (L + 1) * DIM * DIM);
    }

    // ---------------- Pool + head ----------------
    zero_pooled_kernel<<<(G_GRAPH * DIM + TB - 1) / TB, TB>>>();
    pool_kernel<<<(N_NODES * 16 + TB - 1) / TB, TB>>>(batch);
    head_kernel<<<1, 128>>>(fc1w, fc1b, fc2w, fc2b, out);
}

// round 6
// speedup vs baseline: 1.6598x; 1.1371x over previous
#include <cuda_runtime.h>
#include <math.h>

// Problem constants
constexpr int N_NODES = 50000;
constexpr int F_IN    = 128;
constexpr int E_EDGES = 800000;
constexpr int DIM     = 64;
constexpr int G_GRAPH = 128;
constexpr int C_CLS   = 10;
constexpr float BN_EPS = 1e-5f;

// ----------------------------------------------------------------------------
// Device-global scratch (referenced ONLY from device code)
// ----------------------------------------------------------------------------
__device__ float g_agg[N_NODES * DIM];
__device__ float g_u[N_NODES * DIM];
__device__ float g_h[N_NODES * DIM];
__device__ float g_sum[DIM];
__device__ float g_sumsq[DIM];
__device__ float g_scale[DIM];
__device__ float g_shift[DIM];
__device__ float g_Wp[DIM * DIM];          // diag(scale) @ Wa_next
__device__ float g_cvec[DIM];              // shift @ Wa_next
__device__ int   g_deg[N_NODES];
__device__ int   g_gcnt[G_GRAPH];
__device__ int   g_rowstart[N_NODES + 1];
__device__ int   g_cursor[N_NODES];
__device__ int   g_csr[E_EDGES];
__device__ float g_pooled[G_GRAPH * DIM];

enum { BUF_U = 1, BUF_H = 2 };
__device__ __forceinline__ const float* get_buf(int id) {
    return id == BUF_U ? g_u : g_h;
}

__device__ __forceinline__ void red_v4(float* p, float4 v) {
    asm volatile("red.global.add.v4.f32 [%0], {%1,%2,%3,%4};"
                 :: "l"(p), "f"(v.x), "f"(v.y), "f"(v.z), "f"(v.w) : "memory");
}

// ----------------------------------------------------------------------------
// Init: zero deg/gcnt/stats/pooled
// ----------------------------------------------------------------------------
__global__ void init_kernel() {
    int t = blockIdx.x * blockDim.x + threadIdx.x;
    if (t < N_NODES) g_deg[t] = 0;
    if (t < G_GRAPH) g_gcnt[t] = 0;
    if (t < DIM) { g_sum[t] = 0.f; g_sumsq[t] = 0.f; }
    if (t < G_GRAPH * DIM) g_pooled[t] = 0.f;
}

// Histogram degrees + graph counts in one kernel (grid sized by E)
__global__ void counts_kernel(const int* __restrict__ ei,
                              const int* __restrict__ batch) {
    int t = blockIdx.x * blockDim.x + threadIdx.x;
    if (t < E_EDGES) atomicAdd(&g_deg[ei[E_EDGES + t]], 1);
    if (t < N_NODES) atomicAdd(&g_gcnt[batch[t]], 1);
}

// Exclusive scan of deg -> rowstart (+ cursor copy). One block of 1024.
__global__ void scan_kernel() {
    constexpr int CH = (N_NODES + 1023) / 1024;  // 49
    int tid = threadIdx.x;
    int start = tid * CH;
    int s = 0;
    for (int i = 0; i < CH; i++) {
        int idx = start + i;
        if (idx < N_NODES) s += g_deg[idx];
    }
    __shared__ int ps[1024];
    ps[tid] = s;
    __syncthreads();
    for (int off = 1; off < 1024; off <<= 1) {
        int add = (tid >= off) ? ps[tid - off] : 0;
        __syncthreads();
        ps[tid] += add;
        __syncthreads();
    }
    int run = ps[tid] - s;   // exclusive base
    for (int i = 0; i < CH; i++) {
        int idx = start + i;
        if (idx < N_NODES) {
            g_rowstart[idx] = run;
            g_cursor[idx]   = run;
            run += g_deg[idx];
        }
    }
    if (tid == 0) g_rowstart[N_NODES] = E_EDGES;
}

__global__ void place_kernel(const int* __restrict__ ei) {
    int t = blockIdx.x * blockDim.x + threadIdx.x;
    if (t >= E_EDGES) return;
    int dst = ei[E_EDGES + t];
    int pos = atomicAdd(&g_cursor[dst], 1);
    g_csr[pos] = ei[t];
}

// ----------------------------------------------------------------------------
// Per-layer small kernels
// ----------------------------------------------------------------------------
__global__ void bn_params_kernel(const float* __restrict__ gamma,
                                 const float* __restrict__ beta) {
    int j = threadIdx.x;
    if (j >= DIM) return;
    const float inv_n = 1.0f / (float)N_NODES;
    float su = g_sum[j], sq = g_sumsq[j];
    float mean = su * inv_n;
    float var  = sq * inv_n - mean * mean;
    float rstd = rsqrtf(var + BN_EPS);
    float sc = gamma[j] * rstd;
    g_scale[j] = sc;
    g_shift[j] = beta[j] - mean * sc;
    g_sum[j] = 0.f;        // re-zero for next layer's stats
    g_sumsq[j] = 0.f;
}

__global__ void fold_kernel(const float* __restrict__ Wa) {
    int tid = threadIdx.x;   // one block of 256
    for (int i = tid; i < DIM * DIM; i += 256)
        g_Wp[i] = g_scale[i >> 6] * Wa[i];
    if (tid < DIM) {
        float c = 0.f;
        for (int k = 0; k < DIM; k++) c = fmaf(g_shift[k], Wa[k * DIM + tid], c);
        g_cvec[tid] = c;
    }
}

// ----------------------------------------------------------------------------
// CSR gather: g_agg[n] = buf[n] + sum_{nbr} buf[nbr].  Half-warp per node.
// ----------------------------------------------------------------------------
template <int SRC>
__global__ void gather_kernel() {
    int t = blockIdx.x * blockDim.x + threadIdx.x;
    int node = t >> 4;
    int c = t & 15;
    if (node >= N_NODES) return;
    const float4* sp = (const float4*)get_buf(SRC);
    float4 acc = sp[node * 16 + c];
    int s = g_rowstart[node];
    int e = g_rowstart[node + 1];
#pragma unroll 4
    for (int j = s; j < e; j++) {
        int src = __ldg(&g_csr[j]);
        float4 v = sp[src * 16 + c];
        acc.x += v.x; acc.y += v.y; acc.z += v.z; acc.w += v.w;
    }
    ((float4*)g_agg)[node * 16 + c] = acc;
}

// ----------------------------------------------------------------------------
// Register-tiled GEMM core: 256 threads = 64 row-threads x 4 col-groups.
// Each thread: 4 rows x 16 cols.  Block tile: 256 rows x 64 cols.
// MODE: 0 = plain (xw), 1 = pre bias+relu on input (l1b), 2 = deg*cvec (c)
// ----------------------------------------------------------------------------
template <int K, int MODE>
__device__ __forceinline__ void gemm_core(const float* __restrict__ in,
                                          const float* __restrict__ Wsrc,
                                          const float* __restrict__ bin,
                                          const float* __restrict__ bout,
                                          float* __restrict__ out) {
    __shared__ float ws[K * DIM];
    __shared__ float bi_s[DIM], bo_s[DIM], cv_s[DIM];
    int tid = threadIdx.x;
    for (int i = tid; i < K * DIM; i += 256) ws[i] = Wsrc[i];
    if (tid < DIM) {
        bo_s[tid] = bout ? bout[tid] : 0.f;
        if (MODE == 1) bi_s[tid] = bin[tid];
        if (MODE == 2) cv_s[tid] = g_cvec[tid];
    }
    __syncthreads();

    int cg = tid & 3;                 // column group (16 cols)
    int rt = tid >> 2;                // row thread
    int row0 = blockIdx.x * 256 + rt * 4;
    int colbase = cg * 16;

    float acc[4][16];
#pragma unroll
    for (int i = 0; i < 4; i++)
#pragma unroll
        for (int c = 0; c < 16; c++) acc[i][c] = 0.f;

    bool v[4];
#pragma unroll
    for (int i = 0; i < 4; i++) v[i] = (row0 + i) < N_NODES;

    const float4* in4 = (const float4*)in;
    const float4 z4 = make_float4(0.f, 0.f, 0.f, 0.f);

#pragma unroll 2
    for (int k4 = 0; k4 < K / 4; k4++) {
        float4 a[4];
#pragma unroll
        for (int i = 0; i < 4; i++)
            a[i] = v[i] ? in4[(row0 + i) * (K / 4) + k4] : z4;
        if (MODE == 1) {
            float4 b = ((const float4*)bi_s)[k4];
#pragma unroll
            for (int i = 0; i < 4; i++) {
                a[i].x = fmaxf(a[i].x + b.x, 0.f);
                a[i].y = fmaxf(a[i].y + b.y, 0.f);
                a[i].z = fmaxf(a[i].z + b.z, 0.f);
                a[i].w = fmaxf(a[i].w + b.w, 0.f);
            }
        }
#pragma unroll
        for (int kk = 0; kk < 4; kk++) {
            const float* wr = &ws[(k4 * 4 + kk) * DIM + colbase];
            float wv[16];
            *(float4*)(wv + 0)  = *(const float4*)(wr + 0);
            *(float4*)(wv + 4)  = *(const float4*)(wr + 4);
            *(float4*)(wv + 8)  = *(const float4*)(wr + 8);
            *(float4*)(wv + 12) = *(const float4*)(wr + 12);
#pragma unroll
            for (int i = 0; i < 4; i++) {
                const float* ap = (const float*)&a[i];
                float e = ap[kk];
#pragma unroll
                for (int c = 0; c < 16; c++)
                    acc[i][c] = fmaf(e, wv[c], acc[i][c]);
            }
        }
    }

    float4* o4 = (float4*)out;
#pragma unroll
    for (int i = 0; i < 4; i++) {
        if (!v[i]) continue;
        float add16[16];
        if (MODE == 2) {
            float dp1 = 1.0f + (float)g_deg[row0 + i];
#pragma unroll
            for (int c = 0; c < 16; c++)
                add16[c] = fmaf(dp1, cv_s[colbase + c], bo_s[colbase + c]);
        } else {
#pragma unroll
            for (int c = 0; c < 16; c++) add16[c] = bo_s[colbase + c];
        }
#pragma unroll
        for (int c4 = 0; c4 < 4; c4++) {
            float4 r;
            r.x = fmaxf(acc[i][4*c4+0] + add16[4*c4+0], 0.f);
            r.y = fmaxf(acc[i][4*c4+1] + add16[4*c4+1], 0.f);
            r.z = fmaxf(acc[i][4*c4+2] + add16[4*c4+2], 0.f);
            r.w = fmaxf(acc[i][4*c4+3] + add16[4*c4+3], 0.f);
            o4[(row0 + i) * 16 + cg * 4 + c4] = r;
        }
    }
}

// xw = x @ W1a (K=128). NOTE: no relu wanted here, but MODE 0 applies
// relu(acc+0) — xw CAN be negative. So xw uses a dedicated no-relu core.
template <int K>
__global__ __launch_bounds__(256) void gemm_plain_kernel(const float* __restrict__ in,
                                                         const float* __restrict__ W,
                                                         float* __restrict__ outdummy) {
    // plain: out = in @ W  (no bias, no relu); out resolved = g_u
    __shared__ float ws[K * DIM];
    int tid = threadIdx.x;
    for (int i = tid; i < K * DIM; i += 256) ws[i] = W[i];
    __syncthreads();

    int cg = tid & 3;
    int rt = tid >> 2;
    int row0 = blockIdx.x * 256 + rt * 4;
    int colbase = cg * 16;

    float acc[4][16];
#pragma unroll
    for (int i = 0; i < 4; i++)
#pragma unroll
        for (int c = 0; c < 16; c++) acc[i][c] = 0.f;

    bool v[4];
#pragma unroll
    for (int i = 0; i < 4; i++) v[i] = (row0 + i) < N_NODES;

    const float4* in4 = (const float4*)in;
    const float4 z4 = make_float4(0.f, 0.f, 0.f, 0.f);

#pragma unroll 2
    for (int k4 = 0; k4 < K / 4; k4++) {
        float4 a[4];
#pragma unroll
        for (int i = 0; i < 4; i++)
            a[i] = v[i] ? in4[(row0 + i) * (K / 4) + k4] : z4;
#pragma unroll
        for (int kk = 0; kk < 4; kk++) {
            const float* wr = &ws[(k4 * 4 + kk) * DIM + colbase];
            float wv[16];
            *(float4*)(wv + 0)  = *(const float4*)(wr + 0);
            *(float4*)(wv + 4)  = *(const float4*)(wr + 4);
            *(float4*)(wv + 8)  = *(const float4*)(wr + 8);
            *(float4*)(wv + 12) = *(const float4*)(wr + 12);
#pragma unroll
            for (int i = 0; i < 4; i++) {
                const float* ap = (const float*)&a[i];
                float e = ap[kk];
#pragma unroll
                for (int c = 0; c < 16; c++)
                    acc[i][c] = fmaf(e, wv[c], acc[i][c]);
            }
        }
    }

    float4* o4 = (float4*)g_u;
#pragma unroll
    for (int i = 0; i < 4; i++) {
        if (!v[i]) continue;
#pragma unroll
        for (int c4 = 0; c4 < 4; c4++) {
            float4 r = make_float4(acc[i][4*c4+0], acc[i][4*c4+1],
                                   acc[i][4*c4+2], acc[i][4*c4+3]);
            o4[(row0 + i) * 16 + cg * 4 + c4] = r;
        }
    }
}

// l1b: h = relu( relu(agg + b1a) @ W1b + b1b )
__global__ __launch_bounds__(256) void gemm_l1b_kernel(const float* __restrict__ W,
                                                       const float* __restrict__ bin,
                                                       const float* __restrict__ bout) {
    gemm_core<DIM, 1>(g_agg, W, bin, bout, g_h);
}
// c: u = relu( agg @ Wp + (1+deg)*cvec + ba )
__global__ __launch_bounds__(256) void gemm_c_kernel(const float* __restrict__ ba) {
    gemm_core<DIM, 2>(g_agg, g_Wp, nullptr, ba, g_u);
}
// d: h = relu( u @ Wb + bb )
__global__ __launch_bounds__(256) void gemm_d_kernel(const float* __restrict__ W,
                                                     const float* __restrict__ bout) {
    gemm_core<DIM, 0>(g_u, W, nullptr, bout, g_h);
}

// ----------------------------------------------------------------------------
// Column sums / sumsq of g_h
// ----------------------------------------------------------------------------
__global__ void stats_kernel() {
    int tid = threadIdx.x;
    int t0 = blockIdx.x * 256 + tid;
    int stride = gridDim.x * 256;
    float4 s  = make_float4(0,0,0,0);
    float4 s2 = make_float4(0,0,0,0);
    const float4* hp = (const float4*)g_h;
    for (int i = t0; i < N_NODES * 16; i += stride) {
        float4 v = hp[i];
        s.x += v.x; s.y += v.y; s.z += v.z; s.w += v.w;
        s2.x = fmaf(v.x, v.x, s2.x); s2.y = fmaf(v.y, v.y, s2.y);
        s2.z = fmaf(v.z, v.z, s2.z); s2.w = fmaf(v.w, v.w, s2.w);
    }
    __shared__ float4 sh[256], sh2[256];
    sh[tid] = s; sh2[tid] = s2;
    __syncthreads();
    for (int off = 128; off >= 16; off >>= 1) {
        if (tid < off) {
            float4 a = sh[tid], b = sh[tid + off];
            sh[tid] = make_float4(a.x+b.x, a.y+b.y, a.z+b.z, a.w+b.w);
            float4 c = sh2[tid], d = sh2[tid + off];
            sh2[tid] = make_float4(c.x+d.x, c.y+d.y, c.z+d.z, c.w+d.w);
        }
        __syncthreads();
    }
    if (tid < 16) {
        red_v4(g_sum   + tid * 4, sh[tid]);
        red_v4(g_sumsq + tid * 4, sh2[tid]);
    }
}

// ----------------------------------------------------------------------------
// Pool (raw h; BN applied in head)
// ----------------------------------------------------------------------------
__global__ void pool_kernel(const int* __restrict__ batch) {
    int t = blockIdx.x * blockDim.x + threadIdx.x;
    if (t >= N_NODES * 16) return;
    int n = t >> 4;
    int c = t & 15;
    float4 v = ((const float4*)g_h)[t];
    red_v4(g_pooled + batch[n] * DIM + c * 4, v);
}

// ----------------------------------------------------------------------------
// Head
// ----------------------------------------------------------------------------
__global__ void head_kernel(const float* __restrict__ fc1w, const float* __restrict__ fc1b,
                            const float* __restrict__ fc2w, const float* __restrict__ fc2b,
                            float* __restrict__ out) {
    int g = threadIdx.x;
    if (g >= G_GRAPH) return;
    float cnt = (float)g_gcnt[g];
    float p[DIM];
#pragma unroll
    for (int k = 0; k < DIM; k++)
        p[k] = fmaf(g_pooled[g * DIM + k], g_scale[k], cnt * g_shift[k]);

    float z[DIM];
#pragma unroll
    for (int j = 0; j < DIM; j++) z[j] = fc1b[j];
    for (int k = 0; k < DIM; k++) {
        float a = p[k];
#pragma unroll
        for (int j = 0; j < DIM; j++) z[j] = fmaf(a, fc1w[k * DIM + j], z[j]);
    }
#pragma unroll
    for (int j = 0; j < DIM; j++) z[j] = fmaxf(z[j], 0.f);

    float logit[C_CLS];
#pragma unroll
    for (int c = 0; c < C_CLS; c++) logit[c] = fc2b[c];
    for (int j = 0; j < DIM; j++) {
        float a = z[j];
#pragma unroll
        for (int c = 0; c < C_CLS; c++) logit[c] = fmaf(a, fc2w[j * C_CLS + c], logit[c]);
    }

    float m = logit[0];
#pragma unroll
    for (int c = 1; c < C_CLS; c++) m = fmaxf(m, logit[c]);
    float se = 0.f;
#pragma unroll
    for (int c = 0; c < C_CLS; c++) se += expf(logit[c] - m);
    float lse = m + logf(se);
#pragma unroll
    for (int c = 0; c < C_CLS; c++) out[g * C_CLS + c] = logit[c] - lse;
}

// ----------------------------------------------------------------------------
// Launch
// ----------------------------------------------------------------------------
extern "C" void kernel_launch(void* const* d_in, const int* in_sizes, int n_in,
                              void* d_out, int out_size) {
    const float* x     = (const float*)d_in[0];
    const int*   ei    = (const int*)d_in[1];
    const int*   batch = (const int*)d_in[2];
    const float* W1a = (const float*)d_in[3];
    const float* b1a = (const float*)d_in[4];
    const float* W1b = (const float*)d_in[5];
    const float* b1b = (const float*)d_in[6];
    const float* Wa  = (const float*)d_in[7];
    const float* ba  = (const float*)d_in[8];
    const float* Wb  = (const float*)d_in[9];
    const float* bb  = (const float*)d_in[10];
    const float* gammas = (const float*)d_in[11];
    const float* betas  = (const float*)d_in[12];
    const float* fc1w = (const float*)d_in[13];
    const float* fc1b = (const float*)d_in[14];
    const float* fc2w = (const float*)d_in[15];
    const float* fc2b = (const float*)d_in[16];
    float* out = (float*)d_out;

    const int TB = 256;
    const int gemm_blocks = (N_NODES + 255) / 256;            // 196
    const int gath_blocks = (N_NODES * 16 + TB - 1) / TB;     // 3125

    // CSR build + init
    init_kernel<<<(N_NODES + TB - 1) / TB, TB>>>();
    counts_kernel<<<(E_EDGES + TB - 1) / TB, TB>>>(ei, batch);
    scan_kernel<<<1, 1024>>>();
    place_kernel<<<(E_EDGES + TB - 1) / TB, TB>>>(ei);

    // ---------------- Layer 1 ----------------
    gemm_plain_kernel<F_IN><<<gemm_blocks, 256>>>(x, W1a, nullptr); // g_u = x@W1a
    gather_kernel<BUF_U><<<gath_blocks, TB>>>();                    // g_agg = u + sum(nbr u)
    gemm_l1b_kernel<<<gemm_blocks, 256>>>(W1b, b1a, b1b);           // g_h
    stats_kernel<<<296, 256>>>();
    bn_params_kernel<<<1, 64>>>(gammas, betas);
    fold_kernel<<<1, 256>>>(Wa);

    // ---------------- Layers 2..5 ----------------
    for (int L = 0; L < 4; L++) {
        gather_kernel<BUF_H><<<gath_blocks, TB>>>();                // g_agg = h + sum(nbr h)
        gemm_c_kernel<<<gemm_blocks, 256>>>(ba + L * DIM);
        gemm_d_kernel<<<gemm_blocks, 256>>>(Wb + L * DIM * DIM, bb + L * DIM);
        stats_kernel<<<296, 256>>>();
        bn_params_kernel<<<1, 64>>>(gammas + (L + 1) * DIM, betas + (L + 1) * DIM);
        if (L < 3) fold_kernel<<<1, 256>>>(Wa + (L + 1) * DIM * DIM);
    }

    // ---------------- Pool + head ----------------
    pool_kernel<<<gath_blocks, TB>>>(batch);
    head_kernel<<<1, 128>>>(fc1w, fc1b, fc2w, fc2b, out);
}